// round 12
// baseline (speedup 1.0000x reference)
#include <cuda_runtime.h>
#include <cuda_bf16.h>
#include <math.h>

// DynamicRouter: logits = x @ W^T + b + 0.1*noise ; top-2 ; sparse softmax.
// x[B=8,S=4096,D=768] f32, W[E=8,D=768] f32, b[8] f32, noise[B,S,8] f32.
//
// R12: R7 cp.async ring + d-paired fma.rn.f32x2 at TOK=3.
// A conflict-free LDS.128 of W is natively two f32x2 operands, so FFMA2
// needs no repacking (R8's bank-conflict mistake avoided). 48 FFMA2/chunk
// replaces 96 FFMA -> per-warp instruction stream halves; FMA-pipe floor
// drops to ~5.5us, leaving DRAM dominant.

#define D_DIM        768
#define E_DIM        8
#define TOK_PER_WARP 3
#define WARPS        8
#define BLOCK        (WARPS * 32)
#define TOK_PER_BLK  (WARPS * TOK_PER_WARP)   // 24
#define D4           (D_DIM / 4)              // 192
#define NCHUNK       (D4 / 32)                // 6
#define NSTAGE       3
#define SW_F4        (E_DIM * D4)             // 1536 float4 = 24 KB
#define SX_WARP_F4   (NSTAGE * TOK_PER_WARP * 32)   // 288 float4 = 4.5 KB/warp
#define SMEM_BYTES   ((SW_F4 + WARPS * SX_WARP_F4) * 16)  // 61440
#define NOISE_STD    0.1f

#define CP_ASYNC16(dst32, src) \
    asm volatile("cp.async.cg.shared.global [%0], [%1], 16;" \
                 :: "r"(dst32), "l"(src) : "memory")
#define CP_COMMIT() asm volatile("cp.async.commit_group;" ::: "memory")
#define CP_WAIT(n)  asm volatile("cp.async.wait_group %0;" :: "n"(n) : "memory")

// packed f32x2 FMA: acc = a*b + acc (both halves independently)
#define FMA_F32X2(acc, a, b) \
    asm("fma.rn.f32x2 %0, %1, %2, %0;" : "+l"(acc) : "l"(a), "l"(b))
#define UNPACK_F32X2(lo, hi, in) \
    asm("mov.b64 {%0, %1}, %2;" : "=f"(lo), "=f"(hi) : "l"(in))

__global__ __launch_bounds__(BLOCK, 3)
void router_kernel(const float* __restrict__ x,
                   const float* __restrict__ W,
                   const float* __restrict__ b,
                   const float* __restrict__ noise,
                   float* __restrict__ out,
                   int nTokens, int writeIdx)
{
    extern __shared__ float4 smem[];
    float4* sW4 = smem;                 // [E_DIM*D4], 16B lane stride: conflict-free
    float4* sX  = smem + SW_F4;         // ring [WARPS][NSTAGE][TOK*32]

    const int tid  = threadIdx.x;
    const int lane = tid & 31;
    const int wid  = tid >> 5;

    // Stage W into shared once (coalesced float4 copy of contiguous 24 KB)
    {
        const float4* Wg = reinterpret_cast<const float4*>(W);
        #pragma unroll
        for (int i = 0; i < SW_F4 / BLOCK; i++)
            sW4[i * BLOCK + tid] = Wg[i * BLOCK + tid];
    }
    __syncthreads();

    const int tokBase = blockIdx.x * TOK_PER_BLK + wid * TOK_PER_WARP;
    if (tokBase >= nTokens) return;

    // Per-token row pointers, clamped for the partial last warp (duplicate
    // loads of a valid token; results masked at store time).
    const float4* xb = reinterpret_cast<const float4*>(x);
    const float4* xt[TOK_PER_WARP];
    #pragma unroll
    for (int t = 0; t < TOK_PER_WARP; t++) {
        int tk = tokBase + t;
        if (tk > nTokens - 1) tk = nTokens - 1;
        xt[t] = xb + (size_t)tk * D4;
    }

    float4* myX = sX + wid * SX_WARP_F4;
    const unsigned myX32 = (unsigned)__cvta_generic_to_shared(myX);

    // pacc[t][e] = f32x2 {even-d partial, odd-d partial}
    unsigned long long pacc[TOK_PER_WARP][E_DIM];
    #pragma unroll
    for (int t = 0; t < TOK_PER_WARP; t++)
        #pragma unroll
        for (int e = 0; e < E_DIM; e++) pacc[t][e] = 0ull;

    auto issue = [&](int c, int s) {
        #pragma unroll
        for (int t = 0; t < TOK_PER_WARP; t++)
            CP_ASYNC16(myX32 + (unsigned)(((s * TOK_PER_WARP + t) * 32 + lane) * 16),
                       xt[t] + c * 32 + lane);
        CP_COMMIT();
    };

    auto compute = [&](int c, int s) {
        ulonglong2 xv[TOK_PER_WARP];                 // each = 2x f32x2
        #pragma unroll
        for (int t = 0; t < TOK_PER_WARP; t++)
            xv[t] = *reinterpret_cast<const ulonglong2*>(
                        &myX[(s * TOK_PER_WARP + t) * 32 + lane]);
        const int p = c * 32 + lane;
        #pragma unroll
        for (int e = 0; e < E_DIM; e++) {
            const ulonglong2 wv = *reinterpret_cast<const ulonglong2*>(
                                      &sW4[e * D4 + p]);  // conflict-free LDS.128
            #pragma unroll
            for (int t = 0; t < TOK_PER_WARP; t++) {
                FMA_F32X2(pacc[t][e], xv[t].x, wv.x);
                FMA_F32X2(pacc[t][e], xv[t].y, wv.y);
            }
        }
    };

    // fully unrolled 3-deep pipeline over 6 chunks (as R7)
    issue(0, 0); issue(1, 1); issue(2, 2);           // pending: 3
    CP_WAIT(2); compute(0, 0); issue(3, 0);
    CP_WAIT(2); compute(1, 1); issue(4, 1);
    CP_WAIT(2); compute(2, 2); issue(5, 2);
    CP_WAIT(2); compute(3, 0);
    CP_WAIT(1); compute(4, 1);
    CP_WAIT(0); compute(5, 2);

    // Fold packed halves (logit partial = lo + hi), slots 24..31 stay zero.
    float acc[32];
    #pragma unroll
    for (int v = 0; v < 32; v++) acc[v] = 0.0f;
    #pragma unroll
    for (int t = 0; t < TOK_PER_WARP; t++)
        #pragma unroll
        for (int e = 0; e < E_DIM; e++) {
            float lo, hi;
            UNPACK_F32X2(lo, hi, pacc[t][e]);
            acc[t * E_DIM + e] = lo + hi;
        }

    // Log-halving butterfly: lane l ends with the full 32-lane sum of slot l.
    #pragma unroll
    for (int m = 16; m >= 1; m >>= 1) {
        const bool upper = (lane & m) != 0;
        #pragma unroll
        for (int i = 0; i < m; i++) {
            const float lo = acc[i], hi = acc[i + m];
            const float send = upper ? lo : hi;
            const float recv = __shfl_xor_sync(0xFFFFFFFFu, send, m);
            acc[i] = upper ? (hi + recv) : (lo + recv);
        }
    }
    const float sum = acc[0];

    const int t = lane >> 3;            // token within warp (valid when lane<24)
    const int e = lane & 7;             // expert
    const long tok = (long)tokBase + t;
    const bool valid = (lane < TOK_PER_WARP * E_DIM) && (tok < nTokens);

    const float nval = valid ? __ldg(noise + (size_t)tokBase * E_DIM + lane) : 0.0f;
    const float logit = sum + __ldg(b + e) + NOISE_STD * nval;

    // top-1 over each 8-lane expert group (ties -> lower index, jax top_k order)
    float v1 = logit; int i1 = e;
    #pragma unroll
    for (int off = 1; off < 8; off <<= 1) {
        const float ov = __shfl_xor_sync(0xFFFFFFFFu, v1, off);
        const int   oi = __shfl_xor_sync(0xFFFFFFFFu, i1, off);
        if (ov > v1 || (ov == v1 && oi < i1)) { v1 = ov; i1 = oi; }
    }
    // top-2: exclude winner, reduce again
    float v2 = (e == i1) ? -INFINITY : logit; int i2 = e;
    #pragma unroll
    for (int off = 1; off < 8; off <<= 1) {
        const float ov = __shfl_xor_sync(0xFFFFFFFFu, v2, off);
        const int   oi = __shfl_xor_sync(0xFFFFFFFFu, i2, off);
        if (ov > v2 || (ov == v2 && oi < i2)) { v2 = ov; i2 = oi; }
    }

    // 2-element softmax: p1 = 1/(1+exp(v2-v1)), p2 = exp(v2-v1)*p1  (arg <= 0)
    const float ed  = __expf(v2 - v1);
    const float inv = 1.0f / (1.0f + ed);
    const float p   = (e == i1) ? inv : ((e == i2) ? ed * inv : 0.0f);

    if (valid) {
        out[(size_t)tokBase * E_DIM + lane] = p;   // 96B contiguous per warp
        if (writeIdx && e == 0) {
            float* idxOut = out + (size_t)nTokens * E_DIM;
            idxOut[tok * 2 + 0] = (float)i1;
            idxOut[tok * 2 + 1] = (float)i2;
        }
    }
}

extern "C" void kernel_launch(void* const* d_in, const int* in_sizes, int n_in,
                              void* d_out, int out_size)
{
    const float* x     = (const float*)d_in[0];
    const float* W     = (const float*)d_in[1];
    const float* b     = (const float*)d_in[2];
    const float* noise = (const float*)d_in[3];
    float* out = (float*)d_out;

    const int nTokens = in_sizes[3] / E_DIM;          // B*S from noise elem count
    const int writeIdx = (out_size >= nTokens * E_DIM + nTokens * 2) ? 1 : 0;

    // >48KB dynamic smem opt-in (unconditional; idempotent; capture-safe)
    cudaFuncSetAttribute(router_kernel,
                         cudaFuncAttributeMaxDynamicSharedMemorySize,
                         SMEM_BYTES);

    const int grid = (nTokens + TOK_PER_BLK - 1) / TOK_PER_BLK;
    router_kernel<<<grid, BLOCK, SMEM_BYTES>>>(x, W, b, noise, out, nTokens, writeIdx);
}